// round 8
// baseline (speedup 1.0000x reference)
#include <cuda_runtime.h>
#include <cuda_bf16.h>
#include <math.h>
#include <stdint.h>

#define Bb 32
#define Nn 4096
#define Dd 256
#define Kk 128
#define Dc 64

// ---------------- device scratch ----------------
__device__ float g_agg[(size_t)Bb * Kk * Dc];
__device__ float g_mass[Bb * Kk];
// pre-split weights, bf16 hi/lo packed 2-per-word, chunked smem layout
__device__ __align__(16) uint32_t g_WcH[4 * 192 * 32], g_WcL[4 * 192 * 32];
__device__ __align__(16) uint32_t g_W2H[64 * 32],      g_W2L[64 * 32];

// ---------------- smem word-offset layout (32-bit words) ----------------
// stage-1 (double-buffered X slice + W chunk):
#define XB0H 0        // X slice hi [128 tok][36] = 4608
#define XB0L 4608
#define XB1H 9216
#define XB1L 13824    // -> 18432
#define WB0H 18432    // W chunk hi [192 row][36] = 6912
#define WB0L 25344
#define WB1H 32256
#define WB1L 39168    // -> 46080
// phase 2 (aliases stage-1 buffers, temporally disjoint):
#define OFF_AT_H 0        // assign^T hi [128 cl][68] = 8704
#define OFF_AT_L 8704     // -> 17408
#define OFF_H_H  17408    // h hi [128 tok][36] = 4608
#define OFF_H_L  22016    // -> 26624
#define OFF_SQ_H 26624    // sq^T hi [72 d][68] = 4896
#define OFF_SQ_L 31520    // -> 36416
// persistent:
#define OFF_W2_H 46080    // W2 hi [64 f][36] = 2304
#define OFF_W2_L 48384    // -> 50688
#define SMEM_WORDS 50688  // 202752 bytes

// ---------------- helpers ----------------
__device__ __forceinline__ void split2(float x, unsigned short& h, unsigned short& l) {
    __nv_bfloat16 hb = __float2bfloat16_rn(x);
    float lf = x - __bfloat162float(hb);
    h = __bfloat16_as_ushort(hb);
    l = __bfloat16_as_ushort(__float2bfloat16_rn(lf));
}
__device__ __forceinline__ void pack8(const float* v, uint4& H, uint4& L) {
    unsigned short h[8], l[8];
    #pragma unroll
    for (int i = 0; i < 8; i++) split2(v[i], h[i], l[i]);
    H.x = (uint32_t)h[0] | ((uint32_t)h[1] << 16);
    H.y = (uint32_t)h[2] | ((uint32_t)h[3] << 16);
    H.z = (uint32_t)h[4] | ((uint32_t)h[5] << 16);
    H.w = (uint32_t)h[6] | ((uint32_t)h[7] << 16);
    L.x = (uint32_t)l[0] | ((uint32_t)l[1] << 16);
    L.y = (uint32_t)l[2] | ((uint32_t)l[3] << 16);
    L.z = (uint32_t)l[4] | ((uint32_t)l[5] << 16);
    L.w = (uint32_t)l[6] | ((uint32_t)l[7] << 16);
}
__device__ __forceinline__ void mma16(float* d, const uint32_t* a, const uint32_t* b) {
    asm volatile(
        "mma.sync.aligned.m16n8k16.row.col.f32.bf16.bf16.f32 "
        "{%0,%1,%2,%3}, {%4,%5,%6,%7}, {%8,%9}, {%0,%1,%2,%3};"
        : "+f"(d[0]), "+f"(d[1]), "+f"(d[2]), "+f"(d[3])
        : "r"(a[0]), "r"(a[1]), "r"(a[2]), "r"(a[3]), "r"(b[0]), "r"(b[1]));
}
__device__ __forceinline__ void st16s(uint32_t* smu, int word, int half, unsigned short v) {
    ((unsigned short*)&smu[word])[half] = v;
}
__device__ __forceinline__ uint32_t sptr(const void* p) {
    return (uint32_t)__cvta_generic_to_shared(p);
}
#define LDSM4(R0, R1, R2, R3, A) \
    asm volatile("ldmatrix.sync.aligned.m8n8.x4.shared.b16 {%0,%1,%2,%3}, [%4];" \
                 : "=r"(R0), "=r"(R1), "=r"(R2), "=r"(R3) : "r"(A))
#define LDSM2(R0, R1, A) \
    asm volatile("ldmatrix.sync.aligned.m8n8.x2.shared.b16 {%0,%1}, [%2];" \
                 : "=r"(R0), "=r"(R1) : "r"(A))
#define CP16(dst, src) \
    asm volatile("cp.async.cg.shared.global [%0], [%1], 16;" :: "r"(dst), "l"(src))
#define CP_COMMIT() asm volatile("cp.async.commit_group;" ::: "memory")
#define CP_WAIT0()  asm volatile("cp.async.wait_group 0;" ::: "memory")
#define CP_WAIT1()  asm volatile("cp.async.wait_group 1;" ::: "memory")

// ---------------- prep: split weights once into chunked bf16 hi/lo ----------------
__global__ void __launch_bounds__(256) k_prep(const float* __restrict__ W1,
                                              const float* __restrict__ W2,
                                              const float* __restrict__ Wa) {
    int i = blockIdx.x * 256 + threadIdx.x;
    if (i < 24576) {                      // [Wa;W1]: 4 chunks x 192 rows x 32 words
        int c = i / 6144, rem = i % 6144;
        int r = rem >> 5, ww = rem & 31;
        const float* src = (r < 128) ? (Wa + (size_t)r * Dd) : (W1 + (size_t)(r - 128) * Dd);
        float f0 = src[c * 64 + 2 * ww], f1 = src[c * 64 + 2 * ww + 1];
        unsigned short h0, l0, h1, l1;
        split2(f0, h0, l0);
        split2(f1, h1, l1);
        g_WcH[i] = (uint32_t)h0 | ((uint32_t)h1 << 16);
        g_WcL[i] = (uint32_t)l0 | ((uint32_t)l1 << 16);
    } else if (i < 24576 + 2048) {        // W2: 64 rows x 32 words
        int j = i - 24576;
        int r = j >> 5, ww = j & 31;
        float f0 = W2[(size_t)r * 64 + 2 * ww], f1 = W2[(size_t)r * 64 + 2 * ww + 1];
        unsigned short h0, l0, h1, l1;
        split2(f0, h0, l0);
        split2(f1, h1, l1);
        g_W2H[j] = (uint32_t)h0 | ((uint32_t)h1 << 16);
        g_W2L[j] = (uint32_t)l0 | ((uint32_t)l1 << 16);
    }
}

// ---------------- init ----------------
__global__ void __launch_bounds__(256) k_init() {
    int i = blockIdx.x * 256 + threadIdx.x;
    if (i < Bb * Kk * Dc) g_agg[i] = 0.0f;
    else if (i < Bb * Kk * Dc + Bb * Kk) g_mass[i - Bb * Kk * Dc] = 0.0f;
}

// ---------------- fused main kernel: one 128-token tile per block ----------------
__global__ void __launch_bounds__(256, 1) k_fused(
    const float* __restrict__ X,  const float* __restrict__ b1,
    const float* __restrict__ b2, const float* __restrict__ ba)
{
    extern __shared__ float smf[];
    uint32_t* smu = (uint32_t*)smf;
    __shared__ float s_ba[128], s_b1[64], s_b2[64];

    const int tid  = threadIdx.x;
    const int w    = tid >> 5;
    const int lane = tid & 31;
    const int ty   = lane >> 2;
    const int tx   = lane & 3;
    const int b    = blockIdx.x >> 5;
    const int n0t  = (blockIdx.x & 31) * 128;
    const int m0   = w * 16;               // 16 tokens / clusters per warp

    // ldmatrix lane geometry
    const int matq = lane >> 3, rowq = lane & 7;
    const int mrow  = (matq & 1) * 8 + rowq;
    const int acolw = (matq >> 1) * 4;
    const int nrow  = (matq >> 1) * 8 + rowq;
    const int bcolw = (matq & 1) * 4;

    if (tid < 128) s_ba[tid] = ba[tid];
    else if (tid < 192) s_b1[tid - 128] = b1[tid - 128];
    else s_b2[tid - 192] = b2[tid - 192];

    const float4* X4 = (const float4*)(X + (size_t)(b * Nn + n0t) * Dd);
    const int XBH[2] = {XB0H, XB1H}, XBL[2] = {XB0L, XB1L};
    const int WBH[2] = {WB0H, WB1H}, WBL[2] = {WB0L, WB1L};

    // X split for a chunk into a buffer (scalar LDG + cvt + STS)
    auto split_X = [&](int c, int bsel) {
        #pragma unroll
        for (int it = 0; it < 4; it++) {
            int idx = tid + it * 256;            // 0..1023
            int row = idx >> 3, gg = idx & 7;
            const float4* s = X4 + row * 64 + c * 16 + gg * 2;
            float4 f0 = s[0], f1 = s[1];
            float v[8] = {f0.x, f0.y, f0.z, f0.w, f1.x, f1.y, f1.z, f1.w};
            uint4 H, L;
            pack8(v, H, L);
            *(uint4*)&smu[XBH[bsel] + row * 36 + gg * 4] = H;
            *(uint4*)&smu[XBL[bsel] + row * 36 + gg * 4] = L;
        }
    };
    // W chunk via cp.async (pre-split bf16)
    auto issue_W = [&](int c, int bsel) {
        #pragma unroll
        for (int it = 0; it < 6; it++) {
            int idx = tid + it * 256;            // 0..1535
            int row = idx >> 3, seg = idx & 7;
            uint32_t dH = sptr(&smu[WBH[bsel] + row * 36 + seg * 4]);
            uint32_t dL = sptr(&smu[WBL[bsel] + row * 36 + seg * 4]);
            CP16(dH, &g_WcH[c * 6144 + row * 32 + seg * 4]);
            CP16(dL, &g_WcL[c * 6144 + row * 32 + seg * 4]);
        }
    };

    // ---- prologue: chunk 0 + W2 ----
    split_X(0, 0);
    issue_W(0, 0);
    #pragma unroll
    for (int it = 0; it < 2; it++) {
        int idx = tid + it * 256;                // 0..511
        int row = idx >> 3, seg = idx & 7;
        CP16(sptr(&smu[OFF_W2_H + row * 36 + seg * 4]), &g_W2H[row * 32 + seg * 4]);
        CP16(sptr(&smu[OFF_W2_L + row * 36 + seg * 4]), &g_W2L[row * 32 + seg * 4]);
    }
    CP_COMMIT();

    // ---- stage 1: each warp: 16 tokens x 192 cols, K=256 in 4 chunks ----
    float acc1[24][4];
    #pragma unroll
    for (int nb = 0; nb < 24; nb++)
        #pragma unroll
        for (int q = 0; q < 4; q++) acc1[nb][q] = 0.0f;

    uint32_t aXh[2], aXl[2], bW_h[2], bW_l[2];
    #pragma unroll
    for (int s2 = 0; s2 < 2; s2++) {
        aXh[s2] = sptr(&smu[XBH[s2] + (m0 + mrow) * 36 + acolw]);
        aXl[s2] = sptr(&smu[XBL[s2] + (m0 + mrow) * 36 + acolw]);
        bW_h[s2] = sptr(&smu[WBH[s2] + nrow * 36 + bcolw]);
        bW_l[s2] = sptr(&smu[WBL[s2] + nrow * 36 + bcolw]);
    }

    for (int c = 0; c < 4; c++) {
        const int bsel = c & 1;
        if (c < 3) {
            split_X(c + 1, bsel ^ 1);
            issue_W(c + 1, bsel ^ 1);
            CP_COMMIT();
            CP_WAIT1();
        } else {
            CP_WAIT0();
        }
        __syncthreads();

        #pragma unroll
        for (int s = 0; s < 4; s++) {
            const uint32_t off = (uint32_t)(s * 32);      // bytes
            uint32_t ah[4], al[4];
            LDSM4(ah[0], ah[1], ah[2], ah[3], aXh[bsel] + off);
            LDSM4(al[0], al[1], al[2], al[3], aXl[bsel] + off);
            #pragma unroll
            for (int pp = 0; pp < 12; pp++) {
                uint32_t bh[4], bl[4];
                LDSM4(bh[0], bh[1], bh[2], bh[3], bW_h[bsel] + pp * 2304u + off);
                LDSM4(bl[0], bl[1], bl[2], bl[3], bW_l[bsel] + pp * 2304u + off);
                #pragma unroll
                for (int e = 0; e < 2; e++) {
                    const int nb = pp * 2 + e;
                    mma16(acc1[nb], ah, bh + e * 2);
                    mma16(acc1[nb], ah, bl + e * 2);
                    mma16(acc1[nb], al, bh + e * 2);
                }
            }
        }
        __syncthreads();   // compute done before next chunk overwrites other buffer
    }

    // ---- softmax entirely in registers (rows r0=m0+ty, r1=r0+8) ----
    {
        float mx0 = -1e30f, mx1 = -1e30f;
        #pragma unroll
        for (int nb = 0; nb < 16; nb++) {
            const int col = nb * 8 + 2 * tx;
            acc1[nb][0] += s_ba[col];
            acc1[nb][1] += s_ba[col + 1];
            acc1[nb][2] += s_ba[col];
            acc1[nb][3] += s_ba[col + 1];
            mx0 = fmaxf(mx0, fmaxf(acc1[nb][0], acc1[nb][1]));
            mx1 = fmaxf(mx1, fmaxf(acc1[nb][2], acc1[nb][3]));
        }
        mx0 = fmaxf(mx0, __shfl_xor_sync(0xFFFFFFFFu, mx0, 1));
        mx0 = fmaxf(mx0, __shfl_xor_sync(0xFFFFFFFFu, mx0, 2));
        mx1 = fmaxf(mx1, __shfl_xor_sync(0xFFFFFFFFu, mx1, 1));
        mx1 = fmaxf(mx1, __shfl_xor_sync(0xFFFFFFFFu, mx1, 2));
        float s0 = 0.0f, s1 = 0.0f;
        #pragma unroll
        for (int nb = 0; nb < 16; nb++) {
            acc1[nb][0] = __expf(acc1[nb][0] - mx0);
            acc1[nb][1] = __expf(acc1[nb][1] - mx0);
            acc1[nb][2] = __expf(acc1[nb][2] - mx1);
            acc1[nb][3] = __expf(acc1[nb][3] - mx1);
            s0 += acc1[nb][0] + acc1[nb][1];
            s1 += acc1[nb][2] + acc1[nb][3];
        }
        s0 += __shfl_xor_sync(0xFFFFFFFFu, s0, 1);
        s0 += __shfl_xor_sync(0xFFFFFFFFu, s0, 2);
        s1 += __shfl_xor_sync(0xFFFFFFFFu, s1, 1);
        s1 += __shfl_xor_sync(0xFFFFFFFFu, s1, 2);
        const float inv0 = 1.0f / s0, inv1 = 1.0f / s1;
        const int r0 = m0 + ty, r1 = r0 + 8;
        #pragma unroll
        for (int nb = 0; nb < 16; nb++)
            #pragma unroll
            for (int e = 0; e < 2; e++) {
                const int cl = nb * 8 + 2 * tx + e;
                unsigned short hh, ll;
                split2(acc1[nb][e] * inv0, hh, ll);
                st16s(smu, OFF_AT_H + cl * 68 + (r0 >> 1), r0 & 1, hh);
                st16s(smu, OFF_AT_L + cl * 68 + (r0 >> 1), r0 & 1, ll);
                split2(acc1[nb][2 + e] * inv1, hh, ll);
                st16s(smu, OFF_AT_H + cl * 68 + (r1 >> 1), r1 & 1, hh);
                st16s(smu, OFF_AT_L + cl * 68 + (r1 >> 1), r1 & 1, ll);
            }
        // h: cols 128..191 -> bias + LeakyReLU -> H[tok][36]
        #pragma unroll
        for (int nb = 16; nb < 24; nb++)
            #pragma unroll
            for (int e = 0; e < 2; e++) {
                const int eh = (nb - 16) * 8 + 2 * tx + e;
                const int wrd = (nb - 16) * 4 + tx;
                float h0 = acc1[nb][e] + s_b1[eh];
                float h1 = acc1[nb][2 + e] + s_b1[eh];
                h0 = (h0 >= 0.0f) ? h0 : 0.01f * h0;
                h1 = (h1 >= 0.0f) ? h1 : 0.01f * h1;
                unsigned short hh, ll;
                split2(h0, hh, ll);
                st16s(smu, OFF_H_H + r0 * 36 + wrd, e, hh);
                st16s(smu, OFF_H_L + r0 * 36 + wrd, e, ll);
                split2(h1, hh, ll);
                st16s(smu, OFF_H_H + r1 * 36 + wrd, e, hh);
                st16s(smu, OFF_H_L + r1 * 36 + wrd, e, ll);
            }
    }
    __syncthreads();

    // ---- stage 2: sq[128 tok, 64] = h @ W2^T (K=64) ----
    float acc2[8][4];
    #pragma unroll
    for (int nb = 0; nb < 8; nb++)
        #pragma unroll
        for (int q = 0; q < 4; q++) acc2[nb][q] = 0.0f;
    {
        const uint32_t aHh = sptr(&smu[OFF_H_H + (m0 + mrow) * 36 + acolw]);
        const uint32_t aHl = sptr(&smu[OFF_H_L + (m0 + mrow) * 36 + acolw]);
        const uint32_t bWh = sptr(&smu[OFF_W2_H + nrow * 36 + bcolw]);
        const uint32_t bWl = sptr(&smu[OFF_W2_L + nrow * 36 + bcolw]);
        #pragma unroll
        for (int s = 0; s < 4; s++) {
            const uint32_t off = (uint32_t)(s * 32);
            uint32_t ah[4], al[4];
            LDSM4(ah[0], ah[1], ah[2], ah[3], aHh + off);
            LDSM4(al[0], al[1], al[2], al[3], aHl + off);
            #pragma unroll
            for (int pp = 0; pp < 4; pp++) {
                uint32_t bh[4], bl[4];
                LDSM4(bh[0], bh[1], bh[2], bh[3], bWh + pp * 2304u + off);
                LDSM4(bl[0], bl[1], bl[2], bl[3], bWl + pp * 2304u + off);
                #pragma unroll
                for (int e = 0; e < 2; e++) {
                    const int nb = pp * 2 + e;
                    mma16(acc2[nb], ah, bh + e * 2);
                    mma16(acc2[nb], ah, bl + e * 2);
                    mma16(acc2[nb], al, bh + e * 2);
                }
            }
        }
    }

    // ---- write sq^T [d][tok] (+b2) bf16 hi/lo; ones row (d=64) for mass ----
    #pragma unroll
    for (int nb = 0; nb < 8; nb++)
        #pragma unroll
        for (int q = 0; q < 4; q++) {
            int row = m0 + ty + ((q >> 1) << 3);      // token
            int col = nb * 8 + 2 * tx + (q & 1);      // d
            unsigned short hh, ll;
            split2(acc2[nb][q] + s_b2[col], hh, ll);
            st16s(smu, OFF_SQ_H + col * 68 + (row >> 1), row & 1, hh);
            st16s(smu, OFF_SQ_L + col * 68 + (row >> 1), row & 1, ll);
        }
    if (tid < 128) {
        const int tok = tid, wrd = tok >> 1, hf = tok & 1;
        st16s(smu, OFF_SQ_H + 64 * 68 + wrd, hf, (unsigned short)0x3F80);
        st16s(smu, OFF_SQ_L + 64 * 68 + wrd, hf, 0);
        #pragma unroll
        for (int rr = 65; rr < 72; rr++) {
            st16s(smu, OFF_SQ_H + rr * 68 + wrd, hf, 0);
            st16s(smu, OFF_SQ_L + rr * 68 + wrd, hf, 0);
        }
    }
    __syncthreads();

    // ---- stage 3: D3[128 cl, 72] = assign^T @ [sq | 1]  (K=128 tokens) ----
    float acc3[9][4];
    #pragma unroll
    for (int nb = 0; nb < 9; nb++)
        #pragma unroll
        for (int q = 0; q < 4; q++) acc3[nb][q] = 0.0f;
    {
        const uint32_t aAh = sptr(&smu[OFF_AT_H + (m0 + mrow) * 68 + acolw]);
        const uint32_t aAl = sptr(&smu[OFF_AT_L + (m0 + mrow) * 68 + acolw]);
        const uint32_t bSh = sptr(&smu[OFF_SQ_H + nrow * 68 + bcolw]);
        const uint32_t bSl = sptr(&smu[OFF_SQ_L + nrow * 68 + bcolw]);
        const int mat2 = (lane >> 3) & 1;
        const uint32_t b9h = sptr(&smu[OFF_SQ_H + (64 + rowq) * 68 + mat2 * 4]);
        const uint32_t b9l = sptr(&smu[OFF_SQ_L + (64 + rowq) * 68 + mat2 * 4]);

        #pragma unroll
        for (int s = 0; s < 8; s++) {
            const uint32_t off = (uint32_t)(s * 32);
            uint32_t ah[4], al[4];
            LDSM4(ah[0], ah[1], ah[2], ah[3], aAh + off);
            LDSM4(al[0], al[1], al[2], al[3], aAl + off);
            #pragma unroll
            for (int pp = 0; pp < 4; pp++) {
                uint32_t bh[4], bl[4];
                LDSM4(bh[0], bh[1], bh[2], bh[3], bSh + pp * 4352u + off);
                LDSM4(bl[0], bl[1], bl[2], bl[3], bSl + pp * 4352u + off);
                #pragma unroll
                for (int e = 0; e < 2; e++) {
                    const int nb = pp * 2 + e;
                    mma16(acc3[nb], ah, bh + e * 2);
                    mma16(acc3[nb], ah, bl + e * 2);
                    mma16(acc3[nb], al, bh + e * 2);
                }
            }
            {
                uint32_t h9[2], l9[2];
                LDSM2(h9[0], h9[1], b9h + off);
                LDSM2(l9[0], l9[1], b9l + off);
                mma16(acc3[8], ah, h9);
                mma16(acc3[8], ah, l9);
                mma16(acc3[8], al, h9);
            }
        }
    }

    // ---- epilogue: atomics ----
    {
        const size_t base0 = ((size_t)b * Kk + m0 + ty) * Dc;
        #pragma unroll
        for (int nb = 0; nb < 8; nb++) {
            int d0 = nb * 8 + 2 * tx;
            atomicAdd(&g_agg[base0 + d0],              acc3[nb][0]);
            atomicAdd(&g_agg[base0 + d0 + 1],          acc3[nb][1]);
            atomicAdd(&g_agg[base0 + 8 * Dc + d0],     acc3[nb][2]);
            atomicAdd(&g_agg[base0 + 8 * Dc + d0 + 1], acc3[nb][3]);
        }
        if (tx == 0) {
            atomicAdd(&g_mass[b * Kk + m0 + ty],     acc3[8][0]);
            atomicAdd(&g_mass[b * Kk + m0 + ty + 8], acc3[8][2]);
        }
    }
}

// ---------------- finalize: vlad = agg - mass*centroid, L2 normalize ----------------
__global__ void __launch_bounds__(256) k_final(const float* __restrict__ centroid,
                                               float* __restrict__ out) {
    __shared__ float red[256];
    __shared__ float s_inv;
    const int b = blockIdx.x;
    const int tid = threadIdx.x;

    float ss = 0.0f;
    for (int i = tid; i < Kk * Dc; i += 256) {
        int k = i >> 6;
        float v = g_agg[(size_t)b * (Kk * Dc) + i] - g_mass[b * Kk + k] * __ldg(&centroid[i]);
        out[(size_t)b * (Kk * Dc) + i] = v;
        ss += v * v;
    }
    red[tid] = ss;
    __syncthreads();
    #pragma unroll
    for (int s = 128; s > 0; s >>= 1) {
        if (tid < s) red[tid] += red[tid + s];
        __syncthreads();
    }
    if (tid == 0) {
        float n = sqrtf(red[0]);
        s_inv = 1.0f / fmaxf(n, 1e-12f);
    }
    __syncthreads();
    float inv = s_inv;
    for (int i = tid; i < Kk * Dc; i += 256) out[(size_t)b * (Kk * Dc) + i] *= inv;
}

// ---------------- launch ----------------
extern "C" void kernel_launch(void* const* d_in, const int* in_sizes, int n_in,
                              void* d_out, int out_size) {
    const float* X        = (const float*)d_in[0];
    const float* W1       = (const float*)d_in[1];
    const float* b1       = (const float*)d_in[2];
    const float* W2       = (const float*)d_in[3];
    const float* b2       = (const float*)d_in[4];
    const float* Wa       = (const float*)d_in[5];
    const float* ba       = (const float*)d_in[6];
    const float* centroid = (const float*)d_in[7];
    float* out = (float*)d_out;

    cudaFuncSetAttribute(k_fused, cudaFuncAttributeMaxDynamicSharedMemorySize,
                         SMEM_WORDS * 4);

    k_prep<<<104, 256>>>(W1, W2, Wa);
    k_init<<<1040, 256>>>();
    k_fused<<<1024, 256, SMEM_WORDS * 4>>>(X, b1, b2, ba);
    k_final<<<Bb, 256>>>(centroid, out);
}

// round 11
// speedup vs baseline: 1.0881x; 1.0881x over previous
#include <cuda_runtime.h>
#include <cuda_bf16.h>
#include <math.h>
#include <stdint.h>

#define Bb 32
#define Nn 4096
#define Dd 256
#define Kk 128
#define Dc 64

// ---------------- device scratch ----------------
__device__ float g_agg[(size_t)Bb * Kk * Dc];
__device__ float g_mass[Bb * Kk];
__device__ float g_ss[Bb];

// ---------------- smem word-offset layout (32-bit words) ----------------
#define OFF_XH   0        // X hi  [128 tok][132]
#define OFF_XL   16896
#define OFF_WC_H 33792    // W chunk hi [192 row][36]
#define OFF_WC_L 40704
#define OFF_Y    0        // Y fp32 col-major [192 col][132 tok]
#define OFF_AT_H 25344    // assign^T hi [128 cl][68]
#define OFF_AT_L 34048
#define OFF_H_H  42752    // h hi [128 tok][36]
#define OFF_H_L  47360
#define OFF_SQ_H 42752    // sq^T hi [72 d][68] (aliases h after stage 2)
#define OFF_SQ_L 47648
#define OFF_W2_H 52544    // W2 hi [64 f][36]
#define OFF_W2_L 54848
#define SMEM_WORDS 57152  // 228608 bytes

// ---------------- helpers ----------------
__device__ __forceinline__ void split2(float x, unsigned short& h, unsigned short& l) {
    __nv_bfloat16 hb = __float2bfloat16_rn(x);
    float lf = x - __bfloat162float(hb);
    h = __bfloat16_as_ushort(hb);
    l = __bfloat16_as_ushort(__float2bfloat16_rn(lf));
}
__device__ __forceinline__ void pack8(const float* v, uint4& H, uint4& L) {
    unsigned short h[8], l[8];
    #pragma unroll
    for (int i = 0; i < 8; i++) split2(v[i], h[i], l[i]);
    H.x = (uint32_t)h[0] | ((uint32_t)h[1] << 16);
    H.y = (uint32_t)h[2] | ((uint32_t)h[3] << 16);
    H.z = (uint32_t)h[4] | ((uint32_t)h[5] << 16);
    H.w = (uint32_t)h[6] | ((uint32_t)h[7] << 16);
    L.x = (uint32_t)l[0] | ((uint32_t)l[1] << 16);
    L.y = (uint32_t)l[2] | ((uint32_t)l[3] << 16);
    L.z = (uint32_t)l[4] | ((uint32_t)l[5] << 16);
    L.w = (uint32_t)l[6] | ((uint32_t)l[7] << 16);
}
__device__ __forceinline__ void mma16(float* d, const uint32_t* a, const uint32_t* b) {
    asm volatile(
        "mma.sync.aligned.m16n8k16.row.col.f32.bf16.bf16.f32 "
        "{%0,%1,%2,%3}, {%4,%5,%6,%7}, {%8,%9}, {%0,%1,%2,%3};"
        : "+f"(d[0]), "+f"(d[1]), "+f"(d[2]), "+f"(d[3])
        : "r"(a[0]), "r"(a[1]), "r"(a[2]), "r"(a[3]), "r"(b[0]), "r"(b[1]));
}
__device__ __forceinline__ void st16s(uint32_t* smu, int word, int half, unsigned short v) {
    ((unsigned short*)&smu[word])[half] = v;
}
__device__ __forceinline__ uint32_t sptr(const void* p) {
    return (uint32_t)__cvta_generic_to_shared(p);
}
#define LDSM4(R0, R1, R2, R3, A) \
    asm volatile("ldmatrix.sync.aligned.m8n8.x4.shared.b16 {%0,%1,%2,%3}, [%4];" \
                 : "=r"(R0), "=r"(R1), "=r"(R2), "=r"(R3) : "r"(A))
#define LDSM2(R0, R1, A) \
    asm volatile("ldmatrix.sync.aligned.m8n8.x2.shared.b16 {%0,%1}, [%2];" \
                 : "=r"(R0), "=r"(R1) : "r"(A))

// ---------------- init ----------------
__global__ void __launch_bounds__(256) k_init() {
    int i = blockIdx.x * 256 + threadIdx.x;
    if (i < Bb * Kk * Dc) g_agg[i] = 0.0f;
    else if (i < Bb * Kk * Dc + Bb * Kk) g_mass[i - Bb * Kk * Dc] = 0.0f;
    else if (i < Bb * Kk * Dc + Bb * Kk + Bb) g_ss[i - Bb * Kk * Dc - Bb * Kk] = 0.0f;
}

// ---------------- fused main kernel: one 128-token tile per block ----------------
__global__ void __launch_bounds__(256, 1) k_fused(
    const float* __restrict__ X,  const float* __restrict__ W1,
    const float* __restrict__ b1, const float* __restrict__ W2,
    const float* __restrict__ b2, const float* __restrict__ Wa,
    const float* __restrict__ ba)
{
    extern __shared__ float smf[];
    uint32_t* smu = (uint32_t*)smf;
    __shared__ float s_ba[128], s_b1[64], s_b2[64];

    const int tid  = threadIdx.x;
    const int w    = tid >> 5;
    const int lane = tid & 31;
    const int ty   = lane >> 2;
    const int tx   = lane & 3;
    const int b    = blockIdx.x >> 5;
    const int n0t  = (blockIdx.x & 31) * 128;

    // ldmatrix lane geometry
    const int matq = lane >> 3, rowq = lane & 7;
    const int mrow  = (matq & 1) * 8 + rowq;    // A-type: m split on mat bit0
    const int acolw = (matq >> 1) * 4;          // A-type k-word offset
    const int nrow  = (matq >> 1) * 8 + rowq;   // B-type: n split on mat bit1
    const int bcolw = (matq & 1) * 4;           // B-type k-word offset

    if (tid < 128) s_ba[tid] = ba[tid];
    else if (tid < 192) s_b1[tid - 128] = b1[tid - 128];
    else s_b2[tid - 192] = b2[tid - 192];

    // ---- fill: X tile (128x256) split -> bf16 hi/lo; W2 split ----
    {
        const float4* X4 = (const float4*)(X + (size_t)(b * Nn + n0t) * Dd);
        #pragma unroll
        for (int it = 0; it < 16; it++) {
            int idx = tid + it * 256;
            int row = idx >> 5, gg = idx & 31;
            float4 f0 = X4[row * 64 + gg * 2], f1 = X4[row * 64 + gg * 2 + 1];
            float v[8] = {f0.x, f0.y, f0.z, f0.w, f1.x, f1.y, f1.z, f1.w};
            uint4 H, L;
            pack8(v, H, L);
            *(uint4*)&smu[OFF_XH + row * 132 + gg * 4] = H;
            *(uint4*)&smu[OFF_XL + row * 132 + gg * 4] = L;
        }
        #pragma unroll
        for (int it = 0; it < 2; it++) {
            int idx = tid + it * 256;
            int row = idx >> 3, gg = idx & 7;
            const float* src = W2 + (size_t)row * 64 + gg * 8;
            float v[8] = {src[0], src[1], src[2], src[3], src[4], src[5], src[6], src[7]};
            uint4 H, L;
            pack8(v, H, L);
            *(uint4*)&smu[OFF_W2_H + row * 36 + gg * 4] = H;
            *(uint4*)&smu[OFF_W2_L + row * 36 + gg * 4] = L;
        }
    }

    // ---- stage 1: Y[128 tok, 192] = X @ [Wa;W1]^T  (K=256 in 4 chunks) ----
    const int wm = (w & 3) * 32;
    const int wn = (w >> 2) * 96;
    float acc1[2][12][4];
    #pragma unroll
    for (int mt = 0; mt < 2; mt++)
        #pragma unroll
        for (int nb = 0; nb < 12; nb++)
            #pragma unroll
            for (int q = 0; q < 4; q++) acc1[mt][nb][q] = 0.0f;

    uint32_t aAh[2], aAl[2], aBh[6], aBl[6];
    #pragma unroll
    for (int mt = 0; mt < 2; mt++) {
        aAh[mt] = sptr(&smu[OFF_XH + (wm + mt * 16 + mrow) * 132 + acolw]);
        aAl[mt] = sptr(&smu[OFF_XL + (wm + mt * 16 + mrow) * 132 + acolw]);
    }
    #pragma unroll
    for (int pp = 0; pp < 6; pp++) {
        aBh[pp] = sptr(&smu[OFF_WC_H + (wn + pp * 16 + nrow) * 36 + bcolw]);
        aBl[pp] = sptr(&smu[OFF_WC_L + (wn + pp * 16 + nrow) * 36 + bcolw]);
    }

    for (int c = 0; c < 4; c++) {
        __syncthreads();
        #pragma unroll
        for (int it = 0; it < 6; it++) {
            int idx = tid + it * 256;
            int row = idx >> 3, gg = idx & 7;
            const float* src = ((row < 128) ? (Wa + (size_t)row * Dd)
                                            : (W1 + (size_t)(row - 128) * Dd))
                               + c * 64 + gg * 8;
            float v[8] = {src[0], src[1], src[2], src[3], src[4], src[5], src[6], src[7]};
            uint4 H, L;
            pack8(v, H, L);
            *(uint4*)&smu[OFF_WC_H + row * 36 + gg * 4] = H;
            *(uint4*)&smu[OFF_WC_L + row * 36 + gg * 4] = L;
        }
        __syncthreads();

        #pragma unroll
        for (int s = 0; s < 4; s++) {
            const uint32_t offA = (uint32_t)(c * 32 + s * 8) * 4;
            const uint32_t offB = (uint32_t)(s * 8) * 4;
            uint32_t ah[2][4], al[2][4];
            LDSM4(ah[0][0], ah[0][1], ah[0][2], ah[0][3], aAh[0] + offA);
            LDSM4(ah[1][0], ah[1][1], ah[1][2], ah[1][3], aAh[1] + offA);
            LDSM4(al[0][0], al[0][1], al[0][2], al[0][3], aAl[0] + offA);
            LDSM4(al[1][0], al[1][1], al[1][2], al[1][3], aAl[1] + offA);
            #pragma unroll
            for (int pp = 0; pp < 6; pp++) {
                uint32_t bh[4], bl[4];
                LDSM4(bh[0], bh[1], bh[2], bh[3], aBh[pp] + offB);
                LDSM4(bl[0], bl[1], bl[2], bl[3], aBl[pp] + offB);
                #pragma unroll
                for (int e = 0; e < 2; e++) {
                    const int nb = pp * 2 + e;
                    #pragma unroll
                    for (int mt = 0; mt < 2; mt++) {
                        mma16(acc1[mt][nb], ah[mt], bh + e * 2);
                        mma16(acc1[mt][nb], ah[mt], bl + e * 2);
                        mma16(acc1[mt][nb], al[mt], bh + e * 2);
                    }
                }
            }
        }
    }
    __syncthreads();

    // ---- write Y column-major [col][tok] (fp32) ----
    #pragma unroll
    for (int mt = 0; mt < 2; mt++)
        #pragma unroll
        for (int nb = 0; nb < 12; nb++) {
            int row = wm + mt * 16 + ty;
            int col = wn + nb * 8 + 2 * tx;
            smf[OFF_Y + col * 132 + row]           = acc1[mt][nb][0];
            smf[OFF_Y + (col + 1) * 132 + row]     = acc1[mt][nb][1];
            smf[OFF_Y + col * 132 + row + 8]       = acc1[mt][nb][2];
            smf[OFF_Y + (col + 1) * 132 + row + 8] = acc1[mt][nb][3];
        }
    __syncthreads();

    // ---- softmax: 2 threads per token; then h-convert: 2 threads per token ----
    {
        const int tok = tid >> 1;
        const int j0 = (tid & 1) * 64;
        float mx = -1e30f;
        #pragma unroll 8
        for (int j = j0; j < j0 + 64; j++)
            mx = fmaxf(mx, smf[OFF_Y + j * 132 + tok] + s_ba[j]);
        mx = fmaxf(mx, __shfl_xor_sync(0xFFFFFFFFu, mx, 1));
        float ssum = 0.0f;
        #pragma unroll 8
        for (int j = j0; j < j0 + 64; j++) {
            float e = __expf(smf[OFF_Y + j * 132 + tok] + s_ba[j] - mx);
            smf[OFF_Y + j * 132 + tok] = e;
            ssum += e;
        }
        ssum += __shfl_xor_sync(0xFFFFFFFFu, ssum, 1);
        const float inv = 1.0f / ssum;
        const int wrd = tok >> 1, hf = tok & 1;
        #pragma unroll 8
        for (int j = j0; j < j0 + 64; j++) {
            unsigned short hh, ll;
            split2(smf[OFF_Y + j * 132 + tok] * inv, hh, ll);
            st16s(smu, OFF_AT_H + j * 68 + wrd, hf, hh);
            st16s(smu, OFF_AT_L + j * 68 + wrd, hf, ll);
        }
        // h: this thread handles e-range (tid&1)*32..+31 of its token
        #pragma unroll
        for (int g4 = 0; g4 < 4; g4++) {
            const int gg = (tid & 1) * 4 + g4;
            float v[8];
            #pragma unroll
            for (int q = 0; q < 8; q++) {
                int e = gg * 8 + q;
                float h = smf[OFF_Y + (128 + e) * 132 + tok] + s_b1[e];
                v[q] = (h >= 0.0f) ? h : 0.01f * h;
            }
            uint4 H, L;
            pack8(v, H, L);
            *(uint4*)&smu[OFF_H_H + tok * 36 + gg * 4] = H;
            *(uint4*)&smu[OFF_H_L + tok * 36 + gg * 4] = L;
        }
    }
    __syncthreads();

    // ---- stage 2: sq[128 tok, 64] = h @ W2^T (K=64) ----
    const int m0 = w * 16;
    float acc2[8][4];
    #pragma unroll
    for (int nb = 0; nb < 8; nb++)
        #pragma unroll
        for (int q = 0; q < 4; q++) acc2[nb][q] = 0.0f;

    {
        const uint32_t aH2h = sptr(&smu[OFF_H_H + (m0 + mrow) * 36 + acolw]);
        const uint32_t aH2l = sptr(&smu[OFF_H_L + (m0 + mrow) * 36 + acolw]);
        uint32_t aW2h[4], aW2l[4];
        #pragma unroll
        for (int pp = 0; pp < 4; pp++) {
            aW2h[pp] = sptr(&smu[OFF_W2_H + (pp * 16 + nrow) * 36 + bcolw]);
            aW2l[pp] = sptr(&smu[OFF_W2_L + (pp * 16 + nrow) * 36 + bcolw]);
        }
        #pragma unroll
        for (int s = 0; s < 4; s++) {
            const uint32_t off = (uint32_t)(s * 8) * 4;
            uint32_t ah[4], al[4];
            LDSM4(ah[0], ah[1], ah[2], ah[3], aH2h + off);
            LDSM4(al[0], al[1], al[2], al[3], aH2l + off);
            #pragma unroll
            for (int pp = 0; pp < 4; pp++) {
                uint32_t bh[4], bl[4];
                LDSM4(bh[0], bh[1], bh[2], bh[3], aW2h[pp] + off);
                LDSM4(bl[0], bl[1], bl[2], bl[3], aW2l[pp] + off);
                #pragma unroll
                for (int e = 0; e < 2; e++) {
                    const int nb = pp * 2 + e;
                    mma16(acc2[nb], ah, bh + e * 2);
                    mma16(acc2[nb], ah, bl + e * 2);
                    mma16(acc2[nb], al, bh + e * 2);
                }
            }
        }
    }
    __syncthreads();   // all stage-2 reads of h done before sq^T overwrites it

    // ---- write sq^T [d][tok] (+b2) as bf16 hi/lo; append ones row (d=64) ----
    #pragma unroll
    for (int nb = 0; nb < 8; nb++)
        #pragma unroll
        for (int q = 0; q < 4; q++) {
            int row = m0 + ty + ((q >> 1) << 3);      // token
            int col = nb * 8 + 2 * tx + (q & 1);      // d
            unsigned short hh, ll;
            split2(acc2[nb][q] + s_b2[col], hh, ll);
            st16s(smu, OFF_SQ_H + col * 68 + (row >> 1), row & 1, hh);
            st16s(smu, OFF_SQ_L + col * 68 + (row >> 1), row & 1, ll);
        }
    if (tid < 128) {
        const int tok = tid, wrd = tok >> 1, hf = tok & 1;
        st16s(smu, OFF_SQ_H + 64 * 68 + wrd, hf, (unsigned short)0x3F80);
        st16s(smu, OFF_SQ_L + 64 * 68 + wrd, hf, 0);
        #pragma unroll
        for (int rr = 65; rr < 72; rr++) {
            st16s(smu, OFF_SQ_H + rr * 68 + wrd, hf, 0);
            st16s(smu, OFF_SQ_L + rr * 68 + wrd, hf, 0);
        }
    }
    __syncthreads();

    // ---- stage 3: D3[128 cl, 72] = assign^T @ [sq | 1]  (K=128 tokens) ----
    float acc3[9][4];
    #pragma unroll
    for (int nb = 0; nb < 9; nb++)
        #pragma unroll
        for (int q = 0; q < 4; q++) acc3[nb][q] = 0.0f;

    {
        const uint32_t aA3h = sptr(&smu[OFF_AT_H + (m0 + mrow) * 68 + acolw]);
        const uint32_t aA3l = sptr(&smu[OFF_AT_L + (m0 + mrow) * 68 + acolw]);
        uint32_t aB3h[4], aB3l[4];
        #pragma unroll
        for (int pp = 0; pp < 4; pp++) {
            aB3h[pp] = sptr(&smu[OFF_SQ_H + (pp * 16 + nrow) * 68 + bcolw]);
            aB3l[pp] = sptr(&smu[OFF_SQ_L + (pp * 16 + nrow) * 68 + bcolw]);
        }
        const int mat2 = (lane >> 3) & 1;
        const uint32_t aB9h = sptr(&smu[OFF_SQ_H + (64 + rowq) * 68 + mat2 * 4]);
        const uint32_t aB9l = sptr(&smu[OFF_SQ_L + (64 + rowq) * 68 + mat2 * 4]);

        #pragma unroll
        for (int s = 0; s < 8; s++) {
            const uint32_t off = (uint32_t)(s * 8) * 4;
            uint32_t ah[4], al[4];
            LDSM4(ah[0], ah[1], ah[2], ah[3], aA3h + off);
            LDSM4(al[0], al[1], al[2], al[3], aA3l + off);
            #pragma unroll
            for (int pp = 0; pp < 4; pp++) {
                uint32_t bh[4], bl[4];
                LDSM4(bh[0], bh[1], bh[2], bh[3], aB3h[pp] + off);
                LDSM4(bl[0], bl[1], bl[2], bl[3], aB3l[pp] + off);
                #pragma unroll
                for (int e = 0; e < 2; e++) {
                    const int nb = pp * 2 + e;
                    mma16(acc3[nb], ah, bh + e * 2);
                    mma16(acc3[nb], ah, bl + e * 2);
                    mma16(acc3[nb], al, bh + e * 2);
                }
            }
            {
                uint32_t b9h[2], b9l[2];
                LDSM2(b9h[0], b9h[1], aB9h + off);
                LDSM2(b9l[0], b9l[1], aB9l + off);
                mma16(acc3[8], ah, b9h);
                mma16(acc3[8], ah, b9l);
                mma16(acc3[8], al, b9h);
            }
        }
    }

    // ---- epilogue: atomics ----
    {
        const size_t base0 = ((size_t)b * Kk + m0 + ty) * Dc;
        #pragma unroll
        for (int nb = 0; nb < 8; nb++) {
            int d0 = nb * 8 + 2 * tx;
            atomicAdd(&g_agg[base0 + d0],              acc3[nb][0]);
            atomicAdd(&g_agg[base0 + d0 + 1],          acc3[nb][1]);
            atomicAdd(&g_agg[base0 + 8 * Dc + d0],     acc3[nb][2]);
            atomicAdd(&g_agg[base0 + 8 * Dc + d0 + 1], acc3[nb][3]);
        }
        if (tx == 0) {
            atomicAdd(&g_mass[b * Kk + m0 + ty],     acc3[8][0]);
            atomicAdd(&g_mass[b * Kk + m0 + ty + 8], acc3[8][2]);
        }
    }
}

// ---------------- finalize, pass 1: vlad + partial sum-of-squares ----------------
// grid (Bb, 8): each block handles 1024 contiguous elements of batch b.
__global__ void __launch_bounds__(256) k_vlad(const float* __restrict__ centroid,
                                              float* __restrict__ out) {
    const int b = blockIdx.x;
    const int seg = blockIdx.y;
    const int i = seg * 1024 + threadIdx.x * 4;
    const size_t gi = (size_t)b * (Kk * Dc) + i;
    const int k = i >> 6;
    const float m = g_mass[b * Kk + k];     // 16 d-elems per k; i%64 in [0,60] -> same k for all 4
    float4 a = *(const float4*)&g_agg[gi];
    float4 c = *(const float4*)&centroid[i];
    float4 v;
    v.x = a.x - m * c.x;
    v.y = a.y - m * c.y;
    v.z = a.z - m * c.z;
    v.w = a.w - m * c.w;
    *(float4*)&out[gi] = v;
    float ss = v.x * v.x + v.y * v.y + v.z * v.z + v.w * v.w;
    // warp reduce then one atomic per warp
    #pragma unroll
    for (int d = 16; d > 0; d >>= 1) ss += __shfl_xor_sync(0xFFFFFFFFu, ss, d);
    if ((threadIdx.x & 31) == 0) atomicAdd(&g_ss[b], ss);
}

// ---------------- finalize, pass 2: scale by 1/max(norm, eps) ----------------
__global__ void __launch_bounds__(256) k_scale(float* __restrict__ out) {
    const int b = blockIdx.x;
    const float n = sqrtf(g_ss[b]);
    const float inv = 1.0f / fmaxf(n, 1e-12f);
    const int i = blockIdx.y * 1024 + threadIdx.x * 4;
    const size_t gi = (size_t)b * (Kk * Dc) + i;
    float4 v = *(float4*)&out[gi];
    v.x *= inv; v.y *= inv; v.z *= inv; v.w *= inv;
    *(float4*)&out[gi] = v;
}

// ---------------- launch ----------------
extern "C" void kernel_launch(void* const* d_in, const int* in_sizes, int n_in,
                              void* d_out, int out_size) {
    const float* X        = (const float*)d_in[0];
    const float* W1       = (const float*)d_in[1];
    const float* b1       = (const float*)d_in[2];
    const float* W2       = (const float*)d_in[3];
    const float* b2       = (const float*)d_in[4];
    const float* Wa       = (const float*)d_in[5];
    const float* ba       = (const float*)d_in[6];
    const float* centroid = (const float*)d_in[7];
    float* out = (float*)d_out;

    cudaFuncSetAttribute(k_fused, cudaFuncAttributeMaxDynamicSharedMemorySize,
                         SMEM_WORDS * 4);

    k_init<<<1041, 256>>>();
    k_fused<<<1024, 256, SMEM_WORDS * 4>>>(X, W1, b1, W2, b2, Wa, ba);
    dim3 gn(Bb, 8);
    k_vlad<<<gn, 256>>>(centroid, out);
    k_scale<<<gn, 256>>>(out);
}